// round 17
// baseline (speedup 1.0000x reference)
#include <cuda_runtime.h>
#include <math.h>
#include <stdint.h>

#define Bn   32
#define Sn   1024
#define Dn   512
#define Hn   8
#define Ln   4
#define BSn  (Bn*Sn)

// ------------------------- scratch (device globals) -------------------------
__device__ float    g_x[(size_t)BSn * Dn];
__device__ uint32_t g_xpk[(size_t)BSn * 256];
__device__ uint32_t g_qpk[(size_t)256 * 1024 * 32];
__device__ uint32_t g_kpk[(size_t)256 * 1024 * 32];
__device__ uint32_t g_vpk[(size_t)256 * 512 * 64];
__device__ uint32_t g_ctxpk[(size_t)BSn * 256];
__device__ float    g_t1[(size_t)BSn * Dn];
__device__ uint32_t g_t2pk[(size_t)BSn * 256];
__device__ uint32_t g_wqkv[(size_t)Ln * 256 * 1536];
__device__ uint32_t g_wo[(size_t)Ln * 256 * 512];
__device__ uint32_t g_w1[(size_t)Ln * 256 * 512];
__device__ uint32_t g_w2[(size_t)Ln * 256 * 512];
__device__ float    g_logits[BSn];

// pack two fp32 into bf16x2: low half = first arg (even k), high = second
__device__ __forceinline__ uint32_t pk2(float lo, float hi) {
    uint32_t r;
    asm("cvt.rn.bf16x2.f32 %0, %1, %2;" : "=r"(r) : "f"(hi), "f"(lo));
    return r;
}

__device__ __forceinline__ void cpa16(uint32_t dst, const void* src) {
    asm volatile("cp.async.cg.shared.global [%0], [%1], 16;" :: "r"(dst), "l"(src));
}
#define CP_COMMIT() asm volatile("cp.async.commit_group;")
#define CP_WAIT(N)  asm volatile("cp.async.wait_group %0;" :: "n"(N))

#define MMA_BF16(C0,C1,C2,C3,A0,A1,A2,A3,B0,B1)                              \
    asm volatile(                                                            \
        "mma.sync.aligned.m16n8k16.row.col.f32.bf16.bf16.f32 "               \
        "{%0,%1,%2,%3}, {%4,%5,%6,%7}, {%8,%9}, {%0,%1,%2,%3};"              \
        : "+f"(C0), "+f"(C1), "+f"(C2), "+f"(C3)                             \
        : "r"(A0), "r"(A1), "r"(A2), "r"(A3), "r"(B0), "r"(B1))

// ============================ weight pack (all 4, one launch) ===============
#define NQKV (Ln * 256 * 1536)
#define NSQ  (Ln * 256 * 512)
__global__ void pack_all_kernel(const float* __restrict__ Wqkv,
                                const float* __restrict__ Wo,
                                const float* __restrict__ W1,
                                const float* __restrict__ W2,
                                uint32_t* __restrict__ dqkv,
                                uint32_t* __restrict__ dwo,
                                uint32_t* __restrict__ dw1,
                                uint32_t* __restrict__ dw2) {
    int idx = blockIdx.x * 256 + threadIdx.x;
    const float* src; uint32_t* dst; int N; int local;
    if (idx < NQKV)               { src = Wqkv; dst = dqkv; N = 1536; local = idx; }
    else if (idx < NQKV + NSQ)    { src = Wo;   dst = dwo;  N = 512;  local = idx - NQKV; }
    else if (idx < NQKV + 2*NSQ)  { src = W1;   dst = dw1;  N = 512;  local = idx - NQKV - NSQ; }
    else if (idx < NQKV + 3*NSQ)  { src = W2;   dst = dw2;  N = 512;  local = idx - NQKV - 2*NSQ; }
    else return;
    int kp = local / N;
    int n  = local - kp * N;
    dst[local] = pk2(src[(size_t)(2 * kp) * N + n], src[(size_t)(2 * kp + 1) * N + n]);
}

// ============================ embed =========================================
__global__ void embed_kernel(const float* __restrict__ loc,
                             const float* __restrict__ tdist,
                             const float* __restrict__ Wtd,
                             const float* __restrict__ btd,
                             const float* __restrict__ Wemb,
                             const float* __restrict__ bemb,
                             float* __restrict__ x,
                             uint32_t* __restrict__ xpk) {
    int tok = blockIdx.x;
    const float* lp = loc + (size_t)tok * 16;
    const float* tp = tdist + (size_t)tok * 8;
    float in[19];
#pragma unroll
    for (int i = 0; i < 16; i++) in[i] = lp[i];
#pragma unroll
    for (int j = 0; j < 3; j++) {
        float s = btd[j];
#pragma unroll
        for (int i = 0; i < 8; i++) s += tp[i] * Wtd[i * 3 + j];
        in[16 + j] = s;
    }
    int d = threadIdx.x * 4;
    float4 acc = *(const float4*)(bemb + d);
#pragma unroll
    for (int i = 0; i < 19; i++) {
        float4 w = *(const float4*)(Wemb + i * 512 + d);
        float s = in[i];
        acc.x += s * w.x; acc.y += s * w.y; acc.z += s * w.z; acc.w += s * w.w;
    }
    *(float4*)(x + (size_t)tok * 512 + d) = acc;
    uint2 p;
    p.x = pk2(acc.x, acc.y);
    p.y = pk2(acc.z, acc.w);
    *(uint2*)(xpk + (size_t)tok * 256 + threadIdx.x * 2) = p;
}

// ============================ bf16 tensor-core GEMM =========================
// A packed [M][Kp] bf16x2 (k-pairs), W packed [Kp][N].
// Block 128x128, chunk K=32 (16 k-pairs), 3-stage cp.async ring, ONE barrier
// per chunk. 8 warps 2x4, warp tile 64x32.
// MODE 0: fp32 out. MODE 1: relu + packed bf16 out. MODE 2: QKV special.
#define AP 20
#define GEMM_SMEM ((3 * 128 * AP + 3 * 16 * 136) * 4)

template <int MODE>
__global__ __launch_bounds__(256)
void bf16_gemm(const uint32_t* __restrict__ Apk, const uint32_t* __restrict__ Wpk,
               const float* __restrict__ bias,
               float* __restrict__ Cf, uint32_t* __restrict__ Cpk,
               uint32_t* __restrict__ Qpk, uint32_t* __restrict__ Kpk,
               uint32_t* __restrict__ Vpk,
               const int* __restrict__ dlen,
               int M, int N, int Kp) {
    const int bm = blockIdx.y * 128;
    if ((bm & 1023) >= dlen[bm >> 10]) return;   // whole tile invalid

    extern __shared__ uint32_t gsm[];
    uint32_t* AsB = gsm;                     // 3 stages of [128][AP]
    uint32_t* WsB = gsm + 3 * 128 * AP;      // 3 stages of [16][136]

    const int tid  = threadIdx.x;
    const int warp = tid >> 5;
    const int lane = tid & 31;
    const int wm = warp >> 2;
    const int wn = warp & 3;
    const int qid = lane >> 2;
    const int tq  = lane & 3;

    const int bn = blockIdx.x * 128;

    const int arow = tid >> 1;             // 0..127
    const int akp  = (tid & 1) << 3;       // 0 or 8
    const int wkp  = tid >> 4;             // 0..15
    const int wn8  = (tid & 15) << 3;      // 0..120

    const uint32_t* Ag = Apk + (size_t)(bm + arow) * Kp + akp;
    const uint32_t* Wg = Wpk + (size_t)wkp * N + bn + wn8;

    uint32_t aAd[3], aWd[3];
    {
        uint32_t ab = (uint32_t)__cvta_generic_to_shared(AsB);
        uint32_t wb = (uint32_t)__cvta_generic_to_shared(WsB);
#pragma unroll
        for (int i = 0; i < 3; i++) {
            aAd[i] = ab + (i * 128 * AP + arow * AP + akp) * 4;
            aWd[i] = wb + (i * 16 * 136 + wkp * 136 + wn8) * 4;
        }
    }

    const int nck = Kp >> 4;               // chunks of 16 k-pairs

    // prologue: chunks 0 and 1
#pragma unroll
    for (int p = 0; p < 2; p++) {
        if (p < nck) {
            cpa16(aAd[p],      Ag + p * 16);
            cpa16(aAd[p] + 16, Ag + p * 16 + 4);
            cpa16(aWd[p],      Wg + (size_t)p * 16 * N);
            cpa16(aWd[p] + 16, Wg + (size_t)p * 16 * N + 4);
            CP_COMMIT();
        }
    }

    float acc[4][4][4];
#pragma unroll
    for (int i = 0; i < 4; i++)
#pragma unroll
        for (int j = 0; j < 4; j++)
#pragma unroll
            for (int c = 0; c < 4; c++) acc[i][j][c] = 0.f;

    for (int kc = 0; kc < nck; kc++) {
        const int st = kc % 3;
        if (kc + 1 < nck) { CP_WAIT(1); } else { CP_WAIT(0); }
        __syncthreads();   // stage kc ready; stage (kc+2)%3 reads (iter kc-1) done

        if (kc + 2 < nck) {
            const int sn = (kc + 2) % 3;
            cpa16(aAd[sn],      Ag + (kc + 2) * 16);
            cpa16(aAd[sn] + 16, Ag + (kc + 2) * 16 + 4);
            cpa16(aWd[sn],      Wg + (size_t)(kc + 2) * 16 * N);
            cpa16(aWd[sn] + 16, Wg + (size_t)(kc + 2) * 16 * N + 4);
            CP_COMMIT();
        }

        const uint32_t* as_ = AsB + st * 128 * AP;
        const uint32_t* ws_ = WsB + st * 16 * 136;
#pragma unroll
        for (int kk = 0; kk < 16; kk += 8) {
            unsigned a[4][4], b[4][2];
#pragma unroll
            for (int am = 0; am < 4; am++) {
                int m = wm * 64 + am * 16;
                a[am][0] = as_[(m + qid) * AP + kk + tq];
                a[am][1] = as_[(m + qid + 8) * AP + kk + tq];
                a[am][2] = as_[(m + qid) * AP + kk + tq + 4];
                a[am][3] = as_[(m + qid + 8) * AP + kk + tq + 4];
            }
#pragma unroll
            for (int an = 0; an < 4; an++) {
                int n0 = wn * 32 + an * 8;
                b[an][0] = ws_[(kk + tq) * 136 + n0 + qid];
                b[an][1] = ws_[(kk + tq + 4) * 136 + n0 + qid];
            }
#pragma unroll
            for (int am = 0; am < 4; am++)
#pragma unroll
                for (int an = 0; an < 4; an++)
                    MMA_BF16(acc[am][an][0], acc[am][an][1],
                             acc[am][an][2], acc[am][an][3],
                             a[am][0], a[am][1], a[am][2], a[am][3],
                             b[an][0], b[an][1]);
        }
    }

    // epilogue
#pragma unroll
    for (int am = 0; am < 4; am++) {
        int r0 = bm + wm * 64 + am * 16 + qid;
#pragma unroll
        for (int an = 0; an < 4; an++) {
            int col = bn + wn * 32 + an * 8 + 2 * tq;
            float b0 = bias[col], b1 = bias[col + 1];
            float v0 = acc[am][an][0] + b0;
            float v1 = acc[am][an][1] + b1;
            float v2 = acc[am][an][2] + b0;
            float v3 = acc[am][an][3] + b1;
            if (MODE == 0) {
                *(float2*)(Cf + (size_t)r0 * N + col)       = make_float2(v0, v1);
                *(float2*)(Cf + (size_t)(r0 + 8) * N + col) = make_float2(v2, v3);
            } else if (MODE == 1) {
                v0 = fmaxf(v0, 0.f); v1 = fmaxf(v1, 0.f);
                v2 = fmaxf(v2, 0.f); v3 = fmaxf(v3, 0.f);
                Cpk[(size_t)r0 * (N >> 1) + (col >> 1)]       = pk2(v0, v1);
                Cpk[(size_t)(r0 + 8) * (N >> 1) + (col >> 1)] = pk2(v2, v3);
            } else {
                int bb = r0 >> 10;
                int sr = r0 & 1023;
                int h  = (col >> 6) & 7;
                size_t bh = (size_t)(bb * 8 + h);
                if (col < 512) {
                    v0 *= 0.125f; v1 *= 0.125f; v2 *= 0.125f; v3 *= 0.125f;
                    size_t base = (bh * 1024 + sr) * 32 + ((col & 63) >> 1);
                    Qpk[base]            = pk2(v0, v1);
                    Qpk[base + 8 * 32]   = pk2(v2, v3);
                } else if (col < 1024) {
                    size_t base = (bh * 1024 + sr) * 32 + ((col & 63) >> 1);
                    Kpk[base]            = pk2(v0, v1);
                    Kpk[base + 8 * 32]   = pk2(v2, v3);
                } else {
                    // V: key-pair pack via shfl (partner row qid^1 in lane^4)
                    float p0 = __shfl_xor_sync(0xffffffffu, v0, 4);
                    float p1 = __shfl_xor_sync(0xffffffffu, v1, 4);
                    float p2 = __shfl_xor_sync(0xffffffffu, v2, 4);
                    float p3 = __shfl_xor_sync(0xffffffffu, v3, 4);
                    if ((qid & 1) == 0) {
                        int d = col & 63;
                        size_t base = (bh * 512 + (sr >> 1)) * 64 + d;
                        Vpk[base]              = pk2(v0, p0);
                        Vpk[base + 1]          = pk2(v1, p1);
                        Vpk[base + 4 * 64]     = pk2(v2, p2);
                        Vpk[base + 4 * 64 + 1] = pk2(v3, p3);
                    }
                }
            }
        }
    }
}

// ============================ flash attention (bf16 mma, register P) ========
#define QP  36
#define KPT 36
#define VPT 72
#define KTILE (64 * KPT)
#define VTILE (32 * VPT)
#define FSTG (KTILE + VTILE)
#define QTILE (128 * QP)
#define FLASH_SMEM ((2 * FSTG + QTILE) * 4)

__global__ __launch_bounds__(256)
void flash_bf16_kernel(const uint32_t* __restrict__ Qpk,
                       const uint32_t* __restrict__ Kpk,
                       const uint32_t* __restrict__ Vpk,
                       uint32_t* __restrict__ ctxpk,
                       const int* __restrict__ dlen) {
    extern __shared__ uint32_t smu[];

    const int qt = blockIdx.x;
    const int bh = blockIdx.y;
    const int b  = bh >> 3;
    const int len = dlen[b];
    if (qt * 128 >= len) return;
    const int nk = (len + 63) >> 6;

    const int tid = threadIdx.x;
    const int warp = tid >> 5;
    const int lane = tid & 31;
    const int qid = lane >> 2;
    const int tq  = lane & 3;
    const int m0  = warp * 16;

    const uint32_t* Qg = Qpk + ((size_t)bh * 1024 + qt * 128) * 32;
    const uint32_t* Kg = Kpk + (size_t)bh * 1024 * 32;
    const uint32_t* Vg = Vpk + (size_t)bh * 512 * 64;

    uint32_t* Qs = smu + 2 * FSTG;
    uint32_t smbase = (uint32_t)__cvta_generic_to_shared(smu);
    uint32_t qbase  = smbase + 2 * FSTG * 4;

    // group 1: Q tile
#pragma unroll
    for (int u = 0; u < 4; u++) {
        int f = tid + u * 256;
        int r = f >> 3, c4 = (f & 7) << 2;
        cpa16(qbase + (r * QP + c4) * 4, Qg + (size_t)r * 32 + c4);
    }
    CP_COMMIT();
    // group 2: K/V tile 0
    {
        uint32_t kd = smbase, vd = smbase + KTILE * 4;
#pragma unroll
        for (int u = 0; u < 2; u++) {
            int f = tid + u * 256;
            int rk = f >> 3, ck = (f & 7) << 2;
            cpa16(kd + (rk * KPT + ck) * 4, Kg + (size_t)rk * 32 + ck);
            int rv = f >> 4, cv = (f & 15) << 2;
            cpa16(vd + (rv * VPT + cv) * 4, Vg + (size_t)rv * 64 + cv);
        }
        CP_COMMIT();
    }
    CP_WAIT(1);
    __syncthreads();

    // Q fragments: 4 d-chunks of k16
    unsigned aq[4][4];
#pragma unroll
    for (int s = 0; s < 4; s++) {
        aq[s][0] = Qs[(m0 + qid) * QP + s * 8 + tq];
        aq[s][1] = Qs[(m0 + qid + 8) * QP + s * 8 + tq];
        aq[s][2] = Qs[(m0 + qid) * QP + s * 8 + tq + 4];
        aq[s][3] = Qs[(m0 + qid + 8) * QP + s * 8 + tq + 4];
    }

    float mr0 = -1e30f, mr1 = -1e30f, lr0 = 0.f, lr1 = 0.f;
    float O[8][4];
#pragma unroll
    for (int n = 0; n < 8; n++)
#pragma unroll
        for (int c = 0; c < 4; c++) O[n][c] = 0.f;

    for (int kt = 0; kt < nk; kt++) {
        __syncthreads();
        if (kt + 1 < nk) {
            uint32_t sb = smbase + ((kt + 1) & 1) * FSTG * 4;
            uint32_t kd = sb, vd = sb + KTILE * 4;
            const uint32_t* kg = Kg + (size_t)(kt + 1) * 64 * 32;
            const uint32_t* vg = Vg + (size_t)(kt + 1) * 32 * 64;
#pragma unroll
            for (int u = 0; u < 2; u++) {
                int f = tid + u * 256;
                int rk = f >> 3, ck = (f & 7) << 2;
                cpa16(kd + (rk * KPT + ck) * 4, kg + (size_t)rk * 32 + ck);
                int rv = f >> 4, cv = (f & 15) << 2;
                cpa16(vd + (rv * VPT + cv) * 4, vg + (size_t)rv * 64 + cv);
            }
            CP_COMMIT();
            CP_WAIT(1);
        } else {
            CP_WAIT(0);
        }
        __syncthreads();

        const uint32_t* Ks = smu + (kt & 1) * FSTG;
        const uint32_t* Vs = Ks + KTILE;

        // ---- S = Q @ K^T (Q pre-scaled) ----
        float c[8][4];
#pragma unroll
        for (int n = 0; n < 8; n++)
#pragma unroll
            for (int j = 0; j < 4; j++) c[n][j] = 0.f;

#pragma unroll
        for (int s = 0; s < 4; s++) {
#pragma unroll
            for (int n = 0; n < 8; n++) {
                unsigned b0 = Ks[(n * 8 + qid) * KPT + s * 8 + tq];
                unsigned b1 = Ks[(n * 8 + qid) * KPT + s * 8 + tq + 4];
                MMA_BF16(c[n][0], c[n][1], c[n][2], c[n][3],
                         aq[s][0], aq[s][1], aq[s][2], aq[s][3], b0, b1);
            }
        }

        // ---- mask + online softmax (mask ASSIGNS; stale-K can't leak) ----
        const int cb = kt * 64 + 2 * tq;
        float mx0 = -1e30f, mx1 = -1e30f;
#pragma unroll
        for (int n = 0; n < 8; n++) {
            int c0 = cb + n * 8, c1 = c0 + 1;
            if (c0 >= len) { c[n][0] = -1e30f; c[n][2] = -1e30f; }
            if (c1 >= len) { c[n][1] = -1e30f; c[n][3] = -1e30f; }
            mx0 = fmaxf(mx0, fmaxf(c[n][0], c[n][1]));
            mx1 = fmaxf(mx1, fmaxf(c[n][2], c[n][3]));
        }
        mx0 = fmaxf(mx0, __shfl_xor_sync(0xffffffffu, mx0, 1));
        mx0 = fmaxf(mx0, __shfl_xor_sync(0xffffffffu, mx0, 2));
        mx1 = fmaxf(mx1, __shfl_xor_sync(0xffffffffu, mx1, 1));
        mx1 = fmaxf(mx1, __shfl_xor_sync(0xffffffffu, mx1, 2));

        float mn0 = fmaxf(mr0, mx0), mn1 = fmaxf(mr1, mx1);
        float al0 = __expf(mr0 - mn0), al1 = __expf(mr1 - mn1);
        float rs0 = 0.f, rs1 = 0.f;
#pragma unroll
        for (int n = 0; n < 8; n++) {
            c[n][0] = __expf(c[n][0] - mn0);
            c[n][1] = __expf(c[n][1] - mn0);
            c[n][2] = __expf(c[n][2] - mn1);
            c[n][3] = __expf(c[n][3] - mn1);
            rs0 += c[n][0] + c[n][1];
            rs1 += c[n][2] + c[n][3];
        }
        rs0 += __shfl_xor_sync(0xffffffffu, rs0, 1);
        rs0 += __shfl_xor_sync(0xffffffffu, rs0, 2);
        rs1 += __shfl_xor_sync(0xffffffffu, rs1, 1);
        rs1 += __shfl_xor_sync(0xffffffffu, rs1, 2);
        lr0 = lr0 * al0 + rs0;
        lr1 = lr1 * al1 + rs1;
        mr0 = mn0; mr1 = mn1;
#pragma unroll
        for (int n = 0; n < 8; n++) {
            O[n][0] *= al0; O[n][1] *= al0;
            O[n][2] *= al1; O[n][3] *= al1;
        }

        // ---- O += P @ V, P repacked C-frag -> A-frag entirely in registers ----
#pragma unroll
        for (int s = 0; s < 4; s++) {
            unsigned ap0 = pk2(c[2 * s][0],     c[2 * s][1]);
            unsigned ap1 = pk2(c[2 * s][2],     c[2 * s][3]);
            unsigned ap2 = pk2(c[2 * s + 1][0], c[2 * s + 1][1]);
            unsigned ap3 = pk2(c[2 * s + 1][2], c[2 * s + 1][3]);
#pragma unroll
            for (int n = 0; n < 8; n++) {
                unsigned b0 = Vs[(s * 8 + tq) * VPT + n * 8 + qid];
                unsigned b1 = Vs[(s * 8 + tq + 4) * VPT + n * 8 + qid];
                MMA_BF16(O[n][0], O[n][1], O[n][2], O[n][3],
                         ap0, ap1, ap2, ap3, b0, b1);
            }
        }
    }

    // ---- epilogue: packed ctx ----
    float inv0 = 1.f / lr0, inv1 = 1.f / lr1;
    int h = bh & 7;
    size_t row0 = (size_t)(b * Sn + qt * 128 + m0 + qid);
#pragma unroll
    for (int n = 0; n < 8; n++) {
        int dp = h * 32 + 4 * n + tq;
        ctxpk[row0 * 256 + dp]       = pk2(O[n][0] * inv0, O[n][1] * inv0);
        ctxpk[(row0 + 8) * 256 + dp] = pk2(O[n][2] * inv1, O[n][3] * inv1);
    }
}

// ============================ add + layernorm ===============================
__device__ __forceinline__ float blk_sum_128(float v, float* red) {
#pragma unroll
    for (int o = 16; o; o >>= 1) v += __shfl_xor_sync(0xffffffffu, v, o);
    __syncthreads();
    if ((threadIdx.x & 31) == 0) red[threadIdx.x >> 5] = v;
    __syncthreads();
    return red[0] + red[1] + red[2] + red[3];
}

__global__ __launch_bounds__(128)
void add_ln_kernel(float* __restrict__ x, uint32_t* __restrict__ xpk,
                   const float* __restrict__ hh,
                   const float* __restrict__ g, const float* __restrict__ be,
                   const int* __restrict__ dlen) {
    int row = blockIdx.x;
    if ((row & 1023) >= dlen[row >> 10]) return;
    __shared__ float red[4];
    int t = threadIdx.x;
    size_t off = (size_t)row * 512 + t * 4;
    float4 xv = *(float4*)(x + off);
    float4 hv = *(const float4*)(hh + off);
    float v0 = xv.x + hv.x, v1 = xv.y + hv.y, v2 = xv.z + hv.z, v3 = xv.w + hv.w;
    float mean = blk_sum_128(v0 + v1 + v2 + v3, red) * (1.f / 512.f);
    float d0 = v0 - mean, d1 = v1 - mean, d2 = v2 - mean, d3 = v3 - mean;
    float var = blk_sum_128(d0 * d0 + d1 * d1 + d2 * d2 + d3 * d3, red) * (1.f / 512.f);
    float rstd = rsqrtf(var + 1e-5f);
    float4 gv = *(const float4*)(g + t * 4);
    float4 bv = *(const float4*)(be + t * 4);
    float4 o;
    o.x = d0 * rstd * gv.x + bv.x;
    o.y = d1 * rstd * gv.y + bv.y;
    o.z = d2 * rstd * gv.z + bv.z;
    o.w = d3 * rstd * gv.w + bv.w;
    *(float4*)(x + off) = o;
    uint2 p;
    p.x = pk2(o.x, o.y);
    p.y = pk2(o.z, o.w);
    *(uint2*)(xpk + (size_t)row * 256 + t * 2) = p;
}

// ============================ final head ====================================
#define HEAD_SMEM (512 * 32 * 4)

__global__ __launch_bounds__(256)
void final_logits_kernel(const float* __restrict__ x, const float* __restrict__ addr,
                         const float* __restrict__ poi, const int* __restrict__ atype,
                         const float* __restrict__ Wa, const float* __restrict__ ba,
                         const float* __restrict__ Wout, const float* __restrict__ Wcomb,
                         const int* __restrict__ dlen, float* __restrict__ logits) {
    extern __shared__ float ws[];
    for (int i = threadIdx.x; i < 512 * 32; i += 256) ws[i] = Wout[i];
    __syncthreads();

    const int warp = threadIdx.x >> 5;
    const int lane = threadIdx.x & 31;
    const float wc = Wcomb[lane];

    for (int tok = blockIdx.x * 8 + warp; tok < BSn; tok += gridDim.x * 8) {
        int b = tok >> 10;
        int s = tok & 1023;
        if (s >= dlen[b]) continue;
        int t = atype[b];
        float aj = ba[lane]
                 + addr[b]        * Wa[lane]
                 + poi[t * 3 + 0] * Wa[32 + lane]
                 + poi[t * 3 + 1] * Wa[64 + lane]
                 + poi[t * 3 + 2] * Wa[96 + lane];
        const float* xr = x + (size_t)tok * 512;
        float acc = 0.f;
        for (int d0 = 0; d0 < 512; d0 += 32) {
            float xv = xr[d0 + lane];
#pragma unroll
            for (int j = 0; j < 32; j++)
                acc += __shfl_sync(0xffffffffu, xv, j) * ws[(d0 + j) * 32 + lane];
        }
        float tv = tanhf(acc + aj) * wc;
#pragma unroll
        for (int o = 16; o; o >>= 1) tv += __shfl_xor_sync(0xffffffffu, tv, o);
        if (lane == 0) logits[tok] = tv;
    }
}

__global__ __launch_bounds__(256)
void logsoftmax_kernel(const float* __restrict__ logits, const int* __restrict__ dlen,
                       float* __restrict__ out) {
    __shared__ float red[8];
    int b = blockIdx.x;
    int len = dlen[b];
    const float* lg = logits + (size_t)b * Sn;
    float mx = -1e30f;
    for (int s = threadIdx.x; s < len; s += 256) mx = fmaxf(mx, lg[s]);
#pragma unroll
    for (int o = 16; o; o >>= 1) mx = fmaxf(mx, __shfl_xor_sync(0xffffffffu, mx, o));
    if ((threadIdx.x & 31) == 0) red[threadIdx.x >> 5] = mx;
    __syncthreads();
    mx = red[0];
#pragma unroll
    for (int w = 1; w < 8; w++) mx = fmaxf(mx, red[w]);
    __syncthreads();
    float sum = 0.f;
    for (int s = threadIdx.x; s < len; s += 256) sum += expf(lg[s] - mx);
#pragma unroll
    for (int o = 16; o; o >>= 1) sum += __shfl_xor_sync(0xffffffffu, sum, o);
    if ((threadIdx.x & 31) == 0) red[threadIdx.x >> 5] = sum;
    __syncthreads();
    sum = red[0] + red[1] + red[2] + red[3] + red[4] + red[5] + red[6] + red[7];
    float lse = logf(sum) + mx;
    for (int s = threadIdx.x; s < Sn; s += 256)
        out[(size_t)b * Sn + s] = (s < len) ? (lg[s] - lse) : 0.f;
}

// ============================ launch ========================================
extern "C" void kernel_launch(void* const* d_in, const int* in_sizes, int n_in,
                              void* d_out, int out_size) {
    const float* addr  = (const float*)d_in[0];
    const float* loc   = (const float*)d_in[1];
    const float* tdist = (const float*)d_in[2];
    const float* Wtd   = (const float*)d_in[3];
    const float* btd   = (const float*)d_in[4];
    const float* Wemb  = (const float*)d_in[5];
    const float* bemb  = (const float*)d_in[6];
    const float* Wqkv  = (const float*)d_in[7];
    const float* bqkv  = (const float*)d_in[8];
    const float* Wo    = (const float*)d_in[9];
    const float* bo    = (const float*)d_in[10];
    const float* ln1g  = (const float*)d_in[11];
    const float* ln1b  = (const float*)d_in[12];
    const float* W1    = (const float*)d_in[13];
    const float* b1    = (const float*)d_in[14];
    const float* W2    = (const float*)d_in[15];
    const float* b2    = (const float*)d_in[16];
    const float* ln2g  = (const float*)d_in[17];
    const float* ln2b  = (const float*)d_in[18];
    const float* poi   = (const float*)d_in[19];
    const float* Wa    = (const float*)d_in[20];
    const float* ba    = (const float*)d_in[21];
    const float* Wout  = (const float*)d_in[22];
    const float* Wcomb = (const float*)d_in[23];
    const int*   atype = (const int*)d_in[24];
    const int*   dlen  = (const int*)d_in[25];
    float* out = (float*)d_out;

    float *x, *t1, *lg;
    uint32_t *xpk, *qpk, *kpk, *vpk, *ctxpk, *t2pk, *wqkv, *wo, *w1, *w2;
    cudaGetSymbolAddress((void**)&x,     g_x);
    cudaGetSymbolAddress((void**)&xpk,   g_xpk);
    cudaGetSymbolAddress((void**)&qpk,   g_qpk);
    cudaGetSymbolAddress((void**)&kpk,   g_kpk);
    cudaGetSymbolAddress((void**)&vpk,   g_vpk);
    cudaGetSymbolAddress((void**)&ctxpk, g_ctxpk);
    cudaGetSymbolAddress((void**)&t1,    g_t1);
    cudaGetSymbolAddress((void**)&t2pk,  g_t2pk);
    cudaGetSymbolAddress((void**)&wqkv,  g_wqkv);
    cudaGetSymbolAddress((void**)&wo,    g_wo);
    cudaGetSymbolAddress((void**)&w1,    g_w1);
    cudaGetSymbolAddress((void**)&w2,    g_w2);
    cudaGetSymbolAddress((void**)&lg,    g_logits);

    cudaFuncSetAttribute(flash_bf16_kernel,
                         cudaFuncAttributeMaxDynamicSharedMemorySize, FLASH_SMEM);
    cudaFuncSetAttribute(final_logits_kernel,
                         cudaFuncAttributeMaxDynamicSharedMemorySize, HEAD_SMEM);
    cudaFuncSetAttribute(bf16_gemm<0>,
                         cudaFuncAttributeMaxDynamicSharedMemorySize, GEMM_SMEM);
    cudaFuncSetAttribute(bf16_gemm<1>,
                         cudaFuncAttributeMaxDynamicSharedMemorySize, GEMM_SMEM);
    cudaFuncSetAttribute(bf16_gemm<2>,
                         cudaFuncAttributeMaxDynamicSharedMemorySize, GEMM_SMEM);

    pack_all_kernel<<<(NQKV + 3 * NSQ + 255) / 256, 256>>>(Wqkv, Wo, W1, W2,
                                                           wqkv, wo, w1, w2);

    embed_kernel<<<BSn, 128>>>(loc, tdist, Wtd, btd, Wemb, bemb, x, xpk);

    for (int l = 0; l < Ln; l++) {
        bf16_gemm<2><<<dim3(12, 256), 256, GEMM_SMEM>>>(
            xpk, wqkv + (size_t)l * 256 * 1536, bqkv + l * 1536,
            nullptr, nullptr, qpk, kpk, vpk, dlen, BSn, 1536, 256);
        flash_bf16_kernel<<<dim3(8, Bn * Hn), 256, FLASH_SMEM>>>(qpk, kpk, vpk,
                                                                 ctxpk, dlen);
        bf16_gemm<0><<<dim3(4, 256), 256, GEMM_SMEM>>>(
            ctxpk, wo + (size_t)l * 256 * 512, bo + l * 512,
            t1, nullptr, nullptr, nullptr, nullptr, dlen, BSn, 512, 256);
        add_ln_kernel<<<BSn, 128>>>(x, xpk, t1, ln1g + l * 512, ln1b + l * 512, dlen);
        bf16_gemm<1><<<dim3(4, 256), 256, GEMM_SMEM>>>(
            xpk, w1 + (size_t)l * 256 * 512, b1 + l * 512,
            nullptr, t2pk, nullptr, nullptr, nullptr, dlen, BSn, 512, 256);
        bf16_gemm<0><<<dim3(4, 256), 256, GEMM_SMEM>>>(
            t2pk, w2 + (size_t)l * 256 * 512, b2 + l * 512,
            t1, nullptr, nullptr, nullptr, nullptr, dlen, BSn, 512, 256);
        add_ln_kernel<<<BSn, 128>>>(x, xpk, t1, ln2g + l * 512, ln2b + l * 512, dlen);
    }

    final_logits_kernel<<<512, 256, HEAD_SMEM>>>(x, addr, poi, atype, Wa, ba,
                                                 Wout, Wcomb, dlen, lg);
    logsoftmax_kernel<<<Bn, 256>>>(lg, dlen, out);
}